// round 15
// baseline (speedup 1.0000x reference)
#include <cuda_runtime.h>
#include <cstdint>

#define N_NODES 50000
#define N_EDGES 800000
#define IN_DIM  128
#define OUT_DIM 128
#define EDGE_DIM 64

#define ETILE      64                    // edges per tile
#define NTILES_TOT 12500                 // 800000 / 64
#define EGRID      592                   // 148 SMs * occ 4 -> single wave

typedef unsigned long long u64;

// Scratch for node projections (allocation-free per harness rules).
__device__ __align__(16) float g_HU[(size_t)N_NODES * OUT_DIM];
__device__ __align__(16) float g_HW[(size_t)N_NODES * OUT_DIM];
__device__ int g_idx_is64;

__device__ __forceinline__ u64 pack2(float lo, float hi) {
    u64 r; asm("mov.b64 %0, {%1, %2};" : "=l"(r) : "f"(lo), "f"(hi)); return r;
}
__device__ __forceinline__ void fma2(u64& d, u64 a, u64 b) {
    asm("fma.rn.f32x2 %0, %1, %2, %3;" : "=l"(d) : "l"(a), "l"(b), "l"(d));
}
__device__ __forceinline__ float2 unpack2(u64 v) {
    float2 f; asm("mov.b64 {%0, %1}, %2;" : "=f"(f.x), "=f"(f.y) : "l"(v)); return f;
}
__device__ __forceinline__ int fetch_idx(const int* __restrict__ ei32,
                                         int is64, size_t pos) {
    int v = is64 ? ei32[2 * pos] : ei32[pos];
    v = v < 0 ? 0 : (v >= N_NODES ? N_NODES - 1 : v);
    return v;
}

// ---------------------------------------------------------------------------
// Node projection (both W_hu and W_hw via blockIdx.y) — proven kernel.
// Block (0,0) also performs index-dtype detection (edge launches after).
// ---------------------------------------------------------------------------
__global__ __launch_bounds__(256, 2)
void node_proj_kernel(const float* __restrict__ h,
                      const float* __restrict__ Whu,
                      const float* __restrict__ Whw,
                      const int* __restrict__ ei32)
{
    __shared__ __align__(16) float Wsh[32][132];
    __shared__ __align__(16) float Hsh[32][132];

    if (blockIdx.x == 0 && blockIdx.y == 0 && threadIdx.x == 0) {
        int all_zero = 1;
        for (int i = 0; i < 256; ++i)
            if (ei32[2 * i + 1] != 0) { all_zero = 0; break; }
        g_idx_is64 = all_zero;
    }

    const float* __restrict__ W   = blockIdx.y ? Whw : Whu;
    float*       __restrict__ dst = blockIdx.y ? g_HW : g_HU;

    const int tid = threadIdx.x;
    const int tx  = tid & 31;
    const int ty  = tid >> 5;
    const int n0  = blockIdx.x * 128;

    u64 acc[8][4];
#pragma unroll
    for (int p = 0; p < 8; ++p)
#pragma unroll
        for (int j = 0; j < 4; ++j) acc[p][j] = 0ULL;

#pragma unroll 1
    for (int s = 0; s < 4; ++s) {
        __syncthreads();
#pragma unroll
        for (int it = 0; it < 4; ++it) {
            int idx = it * 256 + tid;
            int o   = idx >> 3;
            int kq  = idx & 7;
            float4 w = *reinterpret_cast<const float4*>(W + (size_t)o * IN_DIM + s * 32 + kq * 4);
            Wsh[kq * 4 + 0][o] = w.x; Wsh[kq * 4 + 1][o] = w.y;
            Wsh[kq * 4 + 2][o] = w.z; Wsh[kq * 4 + 3][o] = w.w;
        }
#pragma unroll
        for (int it = 0; it < 4; ++it) {
            int idx = it * 256 + tid;
            int ln  = idx >> 3;
            int kq  = idx & 7;
            int n   = n0 + ln;
            float4 v = make_float4(0.f, 0.f, 0.f, 0.f);
            if (n < N_NODES)
                v = *reinterpret_cast<const float4*>(h + (size_t)n * IN_DIM + s * 32 + kq * 4);
            Hsh[kq * 4 + 0][ln] = v.x; Hsh[kq * 4 + 1][ln] = v.y;
            Hsh[kq * 4 + 2][ln] = v.z; Hsh[kq * 4 + 3][ln] = v.w;
        }
        __syncthreads();

#pragma unroll
        for (int k = 0; k < 32; ++k) {
            float4 w = *reinterpret_cast<const float4*>(&Wsh[k][tx * 4]);
            u64 w2[4];
            w2[0] = pack2(w.x, w.x); w2[1] = pack2(w.y, w.y);
            w2[2] = pack2(w.z, w.z); w2[3] = pack2(w.w, w.w);
            u64 ev[8];
#pragma unroll
            for (int q = 0; q < 4; ++q) {
                ulonglong2 ep = *reinterpret_cast<const ulonglong2*>(&Hsh[k][ty * 16 + q * 4]);
                ev[2 * q] = ep.x; ev[2 * q + 1] = ep.y;
            }
#pragma unroll
            for (int p = 0; p < 8; ++p)
#pragma unroll
                for (int j = 0; j < 4; ++j)
                    fma2(acc[p][j], ev[p], w2[j]);
        }
    }

#pragma unroll
    for (int p = 0; p < 8; ++p) {
        int na = n0 + ty * 16 + 2 * p;
        float2 v0 = unpack2(acc[p][0]), v1 = unpack2(acc[p][1]);
        float2 v2 = unpack2(acc[p][2]), v3 = unpack2(acc[p][3]);
        if (na < N_NODES)
            *reinterpret_cast<float4*>(dst + (size_t)na * OUT_DIM + tx * 4) =
                make_float4(v0.x, v1.x, v2.x, v3.x);
        if (na + 1 < N_NODES)
            *reinterpret_cast<float4*>(dst + (size_t)(na + 1) * OUT_DIM + tx * 4) =
                make_float4(v0.y, v1.y, v2.y, v3.y);
    }
}

// ---------------------------------------------------------------------------
// Fused edge kernel v10: R14 distinct-byte mapping at occupancy 4.
//   lane = out-quad over FULL 128 outs (W LDS.128 distinct, 4wf)
//   warp = 8-edge group (E reads whole-warp broadcast, 1wf)
//   Thread tile 4 edge-pairs x 4 outs (16 u64 accs).
//   Epilogue loads indices per edge-pair (register trim for occ 4).
//   Persistent single wave: grid 592, tiles strided by 592.
// ---------------------------------------------------------------------------
__global__ __launch_bounds__(256, 4)
void edge_kernel(const float* __restrict__ e,
                 const int* __restrict__ ei32,
                 const float* __restrict__ We,
                 float* __restrict__ out)
{
    __shared__ __align__(16) float Wsh[EDGE_DIM][132];   // [k][o]      33.8 KB
    __shared__ __align__(16) float Esh[2][16][68];       // [buf][k][e]  8.7 KB

    const int tid  = threadIdx.x;
    const int lane = tid & 31;   // out-quad: lane*4 .. +3
    const int wy   = tid >> 5;   // edge group: wy*8 .. wy*8+7
    const int bid  = blockIdx.x;
    const int is64 = g_idx_is64;

    // One-time W fill: We[o][kq*4..] -> Wsh[kq*4+j][o], 2048 float4s.
#pragma unroll
    for (int it = 0; it < 8; ++it) {
        int idx = it * 256 + tid;       // 0..2047
        int o   = idx >> 4;             // 0..127
        int kq  = idx & 15;             // 0..15
        float4 w = reinterpret_cast<const float4*>(We)[idx];
        Wsh[kq * 4 + 0][o] = w.x;
        Wsh[kq * 4 + 1][o] = w.y;
        Wsh[kq * 4 + 2][o] = w.z;
        Wsh[kq * 4 + 3][o] = w.w;
    }

    // Stage fill: 64 edges x 16 k = 256 float4 -> 1 per thread.
    const int le = tid >> 2;     // edge within tile 0..63
    const int kq = tid & 3;      // float4 within stage 0..3

    const int ntiles = (NTILES_TOT - bid + EGRID - 1) / EGRID;   // 21 or 22
    const int NS     = 4 * ntiles;

    // Prologue: stage 0 of tile bid into buffer 0.
    float4 pf = *reinterpret_cast<const float4*>(
        e + (size_t)(bid * ETILE + le) * EDGE_DIM + kq * 4);
    Esh[0][kq * 4 + 0][le] = pf.x;
    Esh[0][kq * 4 + 1][le] = pf.y;
    Esh[0][kq * 4 + 2][le] = pf.z;
    Esh[0][kq * 4 + 3][le] = pf.w;
    __syncthreads();

    u64 acc[4][4];

#pragma unroll 1
    for (int gs = 0; gs < NS; ++gs) {
        const int cur = gs & 1;
        const int it  = gs >> 2;
        const int s   = gs & 3;

        // prefetch next stage (possibly next tile's stage 0, stride EGRID)
        if (gs + 1 < NS) {
            const int nit = (gs + 1) >> 2, nss = (gs + 1) & 3;
            const int nt  = bid + nit * EGRID;
            pf = *reinterpret_cast<const float4*>(
                e + (size_t)(nt * ETILE + le) * EDGE_DIM + nss * 16 + kq * 4);
        }

        if (s == 0) {
#pragma unroll
            for (int p = 0; p < 4; ++p)
#pragma unroll
                for (int j = 0; j < 4; ++j) acc[p][j] = 0ULL;
        }

        // ---- 16 k-steps: 1 W LDS.128 (distinct) + 2 E LDS.128 (broadcast)
        //      + 4 dup movs + 16 fma2 ----
#pragma unroll
        for (int k = 0; k < 16; ++k) {
            const int kk = s * 16 + k;
            float4 w = *reinterpret_cast<const float4*>(&Wsh[kk][lane * 4]);
            u64 w2[4];
            w2[0] = pack2(w.x, w.x); w2[1] = pack2(w.y, w.y);
            w2[2] = pack2(w.z, w.z); w2[3] = pack2(w.w, w.w);
            u64 ev[4];
            {
                ulonglong2 ea = *reinterpret_cast<const ulonglong2*>(&Esh[cur][k][wy * 8]);
                ulonglong2 eb = *reinterpret_cast<const ulonglong2*>(&Esh[cur][k][wy * 8 + 4]);
                ev[0] = ea.x; ev[1] = ea.y; ev[2] = eb.x; ev[3] = eb.y;
            }
#pragma unroll
            for (int p = 0; p < 4; ++p)
#pragma unroll
                for (int j = 0; j < 4; ++j)
                    fma2(acc[p][j], ev[p], w2[j]);
        }

        // ---- tile finished: gather + store epilogue (per-pair, reg-lean) ----
        if (s == 3) {
            const int t    = bid + it * EGRID;
            const int base = t * ETILE + wy * 8;     // warp's 8 edges
#pragma unroll
            for (int p = 0; p < 4; ++p) {
                const int ea = base + 2 * p;
                const int sa = fetch_idx(ei32, is64, (size_t)ea);
                const int ta = fetch_idx(ei32, is64, (size_t)N_EDGES + ea);
                const int sb = fetch_idx(ei32, is64, (size_t)ea + 1);
                const int tb = fetch_idx(ei32, is64, (size_t)N_EDGES + ea + 1);

                float2 v0 = unpack2(acc[p][0]), v1 = unpack2(acc[p][1]);
                float2 v2 = unpack2(acc[p][2]), v3 = unpack2(acc[p][3]);

                float4 A = *reinterpret_cast<const float4*>(
                    g_HU + (size_t)sa * OUT_DIM + lane * 4);
                float4 B = *reinterpret_cast<const float4*>(
                    g_HW + (size_t)ta * OUT_DIM + lane * 4);
                float4 C = *reinterpret_cast<const float4*>(
                    g_HU + (size_t)sb * OUT_DIM + lane * 4);
                float4 D = *reinterpret_cast<const float4*>(
                    g_HW + (size_t)tb * OUT_DIM + lane * 4);

                *reinterpret_cast<float4*>(out + (size_t)ea * OUT_DIM + lane * 4) =
                    make_float4(v0.x + A.x + B.x, v1.x + A.y + B.y,
                                v2.x + A.z + B.z, v3.x + A.w + B.w);
                *reinterpret_cast<float4*>(out + (size_t)(ea + 1) * OUT_DIM + lane * 4) =
                    make_float4(v0.y + C.x + D.x, v1.y + C.y + D.y,
                                v2.y + C.z + D.z, v3.y + C.w + D.w);
            }
        }

        // ---- publish prefetched stage into the other buffer ----
        if (gs + 1 < NS) {
            const int nxt = cur ^ 1;
            Esh[nxt][kq * 4 + 0][le] = pf.x;
            Esh[nxt][kq * 4 + 1][le] = pf.y;
            Esh[nxt][kq * 4 + 2][le] = pf.z;
            Esh[nxt][kq * 4 + 3][le] = pf.w;
            __syncthreads();
        }
    }
}

extern "C" void kernel_launch(void* const* d_in, const int* in_sizes, int n_in,
                              void* d_out, int out_size)
{
    const float* h   = (const float*)d_in[0];       // [50000,128]
    const float* e   = (const float*)d_in[1];       // [800000,64]
    const int*   ei  = (const int*)d_in[2];         // [2,800000]
    const float* We  = (const float*)d_in[3];       // [128,64]
    const float* Whu = (const float*)d_in[4];       // [128,128]
    const float* Whw = (const float*)d_in[5];       // [128,128]
    float*       out = (float*)d_out;               // [800000,128]

    dim3 ngrid((N_NODES + 127) / 128, 2);
    node_proj_kernel<<<ngrid, 256>>>(h, Whu, Whw, ei);

    edge_kernel<<<EGRID, 256>>>(e, ei, We, out);
}

// round 16
// speedup vs baseline: 1.0693x; 1.0693x over previous
#include <cuda_runtime.h>
#include <cstdint>

#define N_NODES 50000
#define N_EDGES 800000
#define IN_DIM  128
#define OUT_DIM 128
#define EDGE_DIM 64

#define ETILE      64                    // edges per tile
#define NTILES_TOT 12500                 // 800000 / 64
#define EGRID      444                   // 148 SMs * occ 3 -> single wave

// dynamic smem layout (floats)
#define SMF_W      0                     // Wsh[64][132] = 8448 floats
#define SMF_E      8448                  // Esh[2][32][68] = 4352 floats
#define SM_TOTAL_B ((8448 + 4352) * 4)   // 51200 bytes

typedef unsigned long long u64;

// Scratch for node projections (allocation-free per harness rules).
__device__ __align__(16) float g_HU[(size_t)N_NODES * OUT_DIM];
__device__ __align__(16) float g_HW[(size_t)N_NODES * OUT_DIM];
__device__ int g_idx_is64;

__device__ __forceinline__ u64 pack2(float lo, float hi) {
    u64 r; asm("mov.b64 %0, {%1, %2};" : "=l"(r) : "f"(lo), "f"(hi)); return r;
}
__device__ __forceinline__ void fma2(u64& d, u64 a, u64 b) {
    asm("fma.rn.f32x2 %0, %1, %2, %3;" : "=l"(d) : "l"(a), "l"(b), "l"(d));
}
__device__ __forceinline__ float2 unpack2(u64 v) {
    float2 f; asm("mov.b64 {%0, %1}, %2;" : "=f"(f.x), "=f"(f.y) : "l"(v)); return f;
}
__device__ __forceinline__ int fetch_idx(const int* __restrict__ ei32,
                                         int is64, size_t pos) {
    int v = is64 ? ei32[2 * pos] : ei32[pos];
    v = v < 0 ? 0 : (v >= N_NODES ? N_NODES - 1 : v);
    return v;
}

// ---------------------------------------------------------------------------
// Node projection (both W_hu and W_hw via blockIdx.y) — proven kernel.
// Block (0,0) also performs index-dtype detection (edge launches after).
// ---------------------------------------------------------------------------
__global__ __launch_bounds__(256, 2)
void node_proj_kernel(const float* __restrict__ h,
                      const float* __restrict__ Whu,
                      const float* __restrict__ Whw,
                      const int* __restrict__ ei32)
{
    __shared__ __align__(16) float Wsh[32][132];
    __shared__ __align__(16) float Hsh[32][132];

    if (blockIdx.x == 0 && blockIdx.y == 0 && threadIdx.x == 0) {
        int all_zero = 1;
        for (int i = 0; i < 256; ++i)
            if (ei32[2 * i + 1] != 0) { all_zero = 0; break; }
        g_idx_is64 = all_zero;
    }

    const float* __restrict__ W   = blockIdx.y ? Whw : Whu;
    float*       __restrict__ dst = blockIdx.y ? g_HW : g_HU;

    const int tid = threadIdx.x;
    const int tx  = tid & 31;
    const int ty  = tid >> 5;
    const int n0  = blockIdx.x * 128;

    u64 acc[8][4];
#pragma unroll
    for (int p = 0; p < 8; ++p)
#pragma unroll
        for (int j = 0; j < 4; ++j) acc[p][j] = 0ULL;

#pragma unroll 1
    for (int s = 0; s < 4; ++s) {
        __syncthreads();
#pragma unroll
        for (int it = 0; it < 4; ++it) {
            int idx = it * 256 + tid;
            int o   = idx >> 3;
            int kq  = idx & 7;
            float4 w = *reinterpret_cast<const float4*>(W + (size_t)o * IN_DIM + s * 32 + kq * 4);
            Wsh[kq * 4 + 0][o] = w.x; Wsh[kq * 4 + 1][o] = w.y;
            Wsh[kq * 4 + 2][o] = w.z; Wsh[kq * 4 + 3][o] = w.w;
        }
#pragma unroll
        for (int it = 0; it < 4; ++it) {
            int idx = it * 256 + tid;
            int ln  = idx >> 3;
            int kq  = idx & 7;
            int n   = n0 + ln;
            float4 v = make_float4(0.f, 0.f, 0.f, 0.f);
            if (n < N_NODES)
                v = *reinterpret_cast<const float4*>(h + (size_t)n * IN_DIM + s * 32 + kq * 4);
            Hsh[kq * 4 + 0][ln] = v.x; Hsh[kq * 4 + 1][ln] = v.y;
            Hsh[kq * 4 + 2][ln] = v.z; Hsh[kq * 4 + 3][ln] = v.w;
        }
        __syncthreads();

#pragma unroll
        for (int k = 0; k < 32; ++k) {
            float4 w = *reinterpret_cast<const float4*>(&Wsh[k][tx * 4]);
            u64 w2[4];
            w2[0] = pack2(w.x, w.x); w2[1] = pack2(w.y, w.y);
            w2[2] = pack2(w.z, w.z); w2[3] = pack2(w.w, w.w);
            u64 ev[8];
#pragma unroll
            for (int q = 0; q < 4; ++q) {
                ulonglong2 ep = *reinterpret_cast<const ulonglong2*>(&Hsh[k][ty * 16 + q * 4]);
                ev[2 * q] = ep.x; ev[2 * q + 1] = ep.y;
            }
#pragma unroll
            for (int p = 0; p < 8; ++p)
#pragma unroll
                for (int j = 0; j < 4; ++j)
                    fma2(acc[p][j], ev[p], w2[j]);
        }
    }

#pragma unroll
    for (int p = 0; p < 8; ++p) {
        int na = n0 + ty * 16 + 2 * p;
        float2 v0 = unpack2(acc[p][0]), v1 = unpack2(acc[p][1]);
        float2 v2 = unpack2(acc[p][2]), v3 = unpack2(acc[p][3]);
        if (na < N_NODES)
            *reinterpret_cast<float4*>(dst + (size_t)na * OUT_DIM + tx * 4) =
                make_float4(v0.x, v1.x, v2.x, v3.x);
        if (na + 1 < N_NODES)
            *reinterpret_cast<float4*>(dst + (size_t)(na + 1) * OUT_DIM + tx * 4) =
                make_float4(v0.y, v1.y, v2.y, v3.y);
    }
}

// ---------------------------------------------------------------------------
// Fused edge kernel v11: R14 distinct-byte mapping, occupancy 3, with
//   (a) 32-k stages  -> 2 barriers per tile instead of 4
//   (b) deferred epilogue: publish+barrier BEFORE the gather epilogue, so
//       gather latency overlaps other warps' next-stage compute.
// lane = out-quad over full 128 outs (W LDS.128 distinct, 4wf)
// warp = 8-edge group (E reads whole-warp broadcast)
// Thread tile 4 edge-pairs x 4 outs (16 u64 accs).
// Persistent single wave: grid 444, tiles strided by 444.
// ---------------------------------------------------------------------------
__global__ __launch_bounds__(256, 3)
void edge_kernel(const float* __restrict__ e,
                 const int* __restrict__ ei32,
                 const float* __restrict__ We,
                 float* __restrict__ out)
{
    extern __shared__ __align__(16) float smf[];
    float* Wsh   = smf + SMF_W;    // [64][132]
    float* Ebase = smf + SMF_E;    // [2][32][68]

    const int tid  = threadIdx.x;
    const int lane = tid & 31;   // out-quad: lane*4 .. +3
    const int wy   = tid >> 5;   // edge group: wy*8 .. wy*8+7
    const int bid  = blockIdx.x;
    const int is64 = g_idx_is64;

    // One-time W fill: We[o][kq*4..] -> Wsh[kq*4+j][o], 2048 float4s.
#pragma unroll
    for (int it = 0; it < 8; ++it) {
        int idx = it * 256 + tid;       // 0..2047
        int o   = idx >> 4;             // 0..127
        int kq  = idx & 15;             // 0..15
        float4 w = reinterpret_cast<const float4*>(We)[idx];
        Wsh[(kq * 4 + 0) * 132 + o] = w.x;
        Wsh[(kq * 4 + 1) * 132 + o] = w.y;
        Wsh[(kq * 4 + 2) * 132 + o] = w.z;
        Wsh[(kq * 4 + 3) * 132 + o] = w.w;
    }

    // Stage fill: 64 edges x 32 k = 512 float4 -> 2 per thread.
    const int le0 = tid >> 3,         kq0 = tid & 7;          // idx = tid
    const int le1 = (256 + tid) >> 3, kq1 = (256 + tid) & 7;  // idx = tid+256

    const int ntiles = (NTILES_TOT - bid + EGRID - 1) / EGRID;   // 28 or 29
    const int NS     = 2 * ntiles;

    // Prologue: stage 0 (k 0..31) of tile bid into buffer 0.
    float4 pf0 = *reinterpret_cast<const float4*>(
        e + (size_t)(bid * ETILE + le0) * EDGE_DIM + kq0 * 4);
    float4 pf1 = *reinterpret_cast<const float4*>(
        e + (size_t)(bid * ETILE + le1) * EDGE_DIM + kq1 * 4);
    Ebase[(kq0 * 4 + 0) * 68 + le0] = pf0.x;
    Ebase[(kq0 * 4 + 1) * 68 + le0] = pf0.y;
    Ebase[(kq0 * 4 + 2) * 68 + le0] = pf0.z;
    Ebase[(kq0 * 4 + 3) * 68 + le0] = pf0.w;
    Ebase[(kq1 * 4 + 0) * 68 + le1] = pf1.x;
    Ebase[(kq1 * 4 + 1) * 68 + le1] = pf1.y;
    Ebase[(kq1 * 4 + 2) * 68 + le1] = pf1.z;
    Ebase[(kq1 * 4 + 3) * 68 + le1] = pf1.w;
    __syncthreads();

    u64 acc[4][4];

#pragma unroll 1
    for (int gs = 0; gs < NS; ++gs) {
        const int cur = gs & 1;        // buffer == stage-in-tile
        const int it  = gs >> 1;
        const int s   = gs & 1;
        const float* Ecur = Ebase + cur * (32 * 68);

        // prefetch next stage (possibly next tile's stage 0, stride EGRID)
        if (gs + 1 < NS) {
            const int nit = (gs + 1) >> 1, nss = (gs + 1) & 1;
            const int nt  = bid + nit * EGRID;
            pf0 = *reinterpret_cast<const float4*>(
                e + (size_t)(nt * ETILE + le0) * EDGE_DIM + nss * 32 + kq0 * 4);
            pf1 = *reinterpret_cast<const float4*>(
                e + (size_t)(nt * ETILE + le1) * EDGE_DIM + nss * 32 + kq1 * 4);
        }

        if (s == 0) {
#pragma unroll
            for (int p = 0; p < 4; ++p)
#pragma unroll
                for (int j = 0; j < 4; ++j) acc[p][j] = 0ULL;
        }

        // ---- 32 k-steps: 1 W LDS.128 (distinct) + 2 E LDS.128 (broadcast)
        //      + 4 dup movs + 16 fma2 per k ----
#pragma unroll
        for (int k = 0; k < 32; ++k) {
            const int kk = s * 32 + k;
            float4 w = *reinterpret_cast<const float4*>(&Wsh[kk * 132 + lane * 4]);
            u64 w2[4];
            w2[0] = pack2(w.x, w.x); w2[1] = pack2(w.y, w.y);
            w2[2] = pack2(w.z, w.z); w2[3] = pack2(w.w, w.w);
            u64 ev[4];
            {
                ulonglong2 ea = *reinterpret_cast<const ulonglong2*>(&Ecur[k * 68 + wy * 8]);
                ulonglong2 eb = *reinterpret_cast<const ulonglong2*>(&Ecur[k * 68 + wy * 8 + 4]);
                ev[0] = ea.x; ev[1] = ea.y; ev[2] = eb.x; ev[3] = eb.y;
            }
#pragma unroll
            for (int p = 0; p < 4; ++p)
#pragma unroll
                for (int j = 0; j < 4; ++j)
                    fma2(acc[p][j], ev[p], w2[j]);
        }

        // ---- publish prefetched stage + barrier FIRST (epilogue deferred) ----
        if (gs + 1 < NS) {
            float* En = Ebase + (cur ^ 1) * (32 * 68);
            En[(kq0 * 4 + 0) * 68 + le0] = pf0.x;
            En[(kq0 * 4 + 1) * 68 + le0] = pf0.y;
            En[(kq0 * 4 + 2) * 68 + le0] = pf0.z;
            En[(kq0 * 4 + 3) * 68 + le0] = pf0.w;
            En[(kq1 * 4 + 0) * 68 + le1] = pf1.x;
            En[(kq1 * 4 + 1) * 68 + le1] = pf1.y;
            En[(kq1 * 4 + 2) * 68 + le1] = pf1.z;
            En[(kq1 * 4 + 3) * 68 + le1] = pf1.w;
            __syncthreads();
        }

        // ---- deferred epilogue: overlaps other warps' next-stage compute ----
        if (s == 1) {
            const int t    = bid + it * EGRID;
            const int base = t * ETILE + wy * 8;     // warp's 8 edges
            int sidx[8], tidx[8];
#pragma unroll
            for (int i = 0; i < 8; ++i) {
                sidx[i] = fetch_idx(ei32, is64, (size_t)(base + i));
                tidx[i] = fetch_idx(ei32, is64, (size_t)N_EDGES + base + i);
            }
#pragma unroll
            for (int p = 0; p < 4; ++p) {
                const int ea = base + 2 * p;
                float2 v0 = unpack2(acc[p][0]), v1 = unpack2(acc[p][1]);
                float2 v2 = unpack2(acc[p][2]), v3 = unpack2(acc[p][3]);

                float4 A = *reinterpret_cast<const float4*>(
                    g_HU + (size_t)sidx[2 * p] * OUT_DIM + lane * 4);
                float4 B = *reinterpret_cast<const float4*>(
                    g_HW + (size_t)tidx[2 * p] * OUT_DIM + lane * 4);
                float4 C = *reinterpret_cast<const float4*>(
                    g_HU + (size_t)sidx[2 * p + 1] * OUT_DIM + lane * 4);
                float4 D = *reinterpret_cast<const float4*>(
                    g_HW + (size_t)tidx[2 * p + 1] * OUT_DIM + lane * 4);

                *reinterpret_cast<float4*>(out + (size_t)ea * OUT_DIM + lane * 4) =
                    make_float4(v0.x + A.x + B.x, v1.x + A.y + B.y,
                                v2.x + A.z + B.z, v3.x + A.w + B.w);
                *reinterpret_cast<float4*>(out + (size_t)(ea + 1) * OUT_DIM + lane * 4) =
                    make_float4(v0.y + C.x + D.x, v1.y + C.y + D.y,
                                v2.y + C.z + D.z, v3.y + C.w + D.w);
            }
        }
    }
}

extern "C" void kernel_launch(void* const* d_in, const int* in_sizes, int n_in,
                              void* d_out, int out_size)
{
    const float* h   = (const float*)d_in[0];       // [50000,128]
    const float* e   = (const float*)d_in[1];       // [800000,64]
    const int*   ei  = (const int*)d_in[2];         // [2,800000]
    const float* We  = (const float*)d_in[3];       // [128,64]
    const float* Whu = (const float*)d_in[4];       // [128,128]
    const float* Whw = (const float*)d_in[5];       // [128,128]
    float*       out = (float*)d_out;               // [800000,128]

    dim3 ngrid((N_NODES + 127) / 128, 2);
    node_proj_kernel<<<ngrid, 256>>>(h, Whu, Whw, ei);

    cudaFuncSetAttribute(edge_kernel,
                         cudaFuncAttributeMaxDynamicSharedMemorySize, SM_TOTAL_B);
    edge_kernel<<<EGRID, 256, SM_TOTAL_B>>>(e, ei, We, out);
}